// round 16
// baseline (speedup 1.0000x reference)
#include <cuda_runtime.h>

// GumbelTopK forward == per row: 1.0 at positions of the top-64 values of
// (logits + gumbel_noise), ties -> lowest index; 0.0 elsewhere.
// (cumsum(softmax) <= 64 is always all-ones; straight-through makes the
// forward value exactly y_hard; softmax is monotone so top_k(y)==top_k(g).)

#define NTHREADS 256
#define N_COLS   8192
#define TOPK     64u
#define CAP      512
#define VEC      8      // float4/uint4 chunks per thread

__device__ __forceinline__ unsigned ordkey(float f) {
    unsigned u = __float_as_uint(f);
    return (u & 0x80000000u) ? ~u : (u | 0x80000000u);
}

__global__ __launch_bounds__(NTHREADS, 5) void gumbel_topk_kernel(
    const float* __restrict__ logits,
    const float* __restrict__ noise,
    float* __restrict__ out)
{
    __shared__ unsigned skey[N_COLS];          // 32 KB: keys live here, not in regs
    __shared__ unsigned hist[1024];            // 2048 bins packed as 2x16-bit
    __shared__ unsigned wsum[8];
    __shared__ unsigned s_prefix, s_need, s_c, s_cnt;
    __shared__ unsigned listKey[CAP];
    __shared__ unsigned short listIdx[CAP];

    const int t    = threadIdx.x;
    const int lane = t & 31;
    const int w    = t >> 5;
    const int row  = blockIdx.x;

    const float4* L = (const float4*)logits + (size_t)row * (N_COLS / 4);
    const float4* G = (const float4*)noise  + (size_t)row * (N_COLS / 4);
    uint4* SK4 = (uint4*)skey;

    // zero 2048-bin histogram (packed)
    for (int i = t; i < 1024; i += NTHREADS) hist[i] = 0;
    __syncthreads();

    // ---- load + key transform + fused 11-bit histogram (warp-aggregated) ----
#pragma unroll
    for (int j = 0; j < VEC; j++) {
        float4 a = L[j * NTHREADS + t];
        float4 b = G[j * NTHREADS + t];
        uint4 k;
        k.x = ordkey(a.x + b.x);
        k.y = ordkey(a.y + b.y);
        k.z = ordkey(a.z + b.z);
        k.w = ordkey(a.w + b.w);
        SK4[j * NTHREADS + t] = k;
        unsigned kk[4] = {k.x, k.y, k.z, k.w};
#pragma unroll
        for (int q = 0; q < 4; q++) {
            unsigned bin = kk[q] >> 21;                       // 11-bit bucket
            unsigned m = __match_any_sync(0xFFFFFFFFu, bin);
            if ((unsigned)(__ffs(m) - 1) == lane)
                atomicAdd(&hist[bin >> 1],
                          (unsigned)__popc(m) << ((bin & 1) * 16));
        }
    }
    __syncthreads();

    // ---- pass 1 selection: suffix counts over 2048 bins (8 bins/thread) ----
    unsigned need = TOPK, prefix, pmask, csel;
    {
        uint4 hv = ((const uint4*)hist)[t];                   // bins t*8..t*8+7
        unsigned c[8];
        c[0] = hv.x & 0xFFFFu; c[1] = hv.x >> 16;
        c[2] = hv.y & 0xFFFFu; c[3] = hv.y >> 16;
        c[4] = hv.z & 0xFFFFu; c[5] = hv.z >> 16;
        c[6] = hv.w & 0xFFFFu; c[7] = hv.w >> 16;
        unsigned g = c[0]+c[1]+c[2]+c[3]+c[4]+c[5]+c[6]+c[7];
        unsigned s = g;
#pragma unroll
        for (int d = 1; d < 32; d <<= 1) {
            unsigned o = __shfl_down_sync(0xFFFFFFFFu, s, d);
            if (lane + d < 32) s += o;
        }
        if (lane == 0) wsum[w] = s;
        __syncthreads();
        if (t == 0) {
            unsigned tmp[8], run = 0;
            for (int i = 7; i >= 0; i--) { tmp[i] = run; run += wsum[i]; }
            for (int i = 0; i < 8; i++) wsum[i] = tmp[i];
        }
        __syncthreads();
        unsigned run = (s - g) + wsum[w];      // elements in bins above my group
#pragma unroll
        for (int b2 = 7; b2 >= 0; b2--) {
            unsigned cb = c[b2];
            if (run < need && run + cb >= need) {   // exactly one (t,b2) matches
                s_prefix = ((unsigned)(t * 8 + b2)) << 21;
                s_need   = need - run;
                s_c      = cb;
            }
            run += cb;
        }
        __syncthreads();
        prefix = s_prefix; need = s_need; csel = s_c;
        pmask  = 0xFFE00000u;
    }

    // ---- rare fallback passes: 8-bit refinements until candidates <= CAP ----
    const int fshift[3] = {13, 5, 0};
    for (int p = 0; p < 3; p++) {
        if (csel <= CAP) break;
        __syncthreads();                        // retire prior hist/wsum readers
        if (t < 128) hist[t] = 0;
        __syncthreads();
        const int shift = fshift[p];
#pragma unroll
        for (int j = 0; j < VEC; j++) {
            uint4 k = SK4[j * NTHREADS + t];
            unsigned kk[4] = {k.x, k.y, k.z, k.w};
#pragma unroll
            for (int q = 0; q < 4; q++)
                if ((kk[q] & pmask) == prefix) {
                    unsigned bin = (kk[q] >> shift) & 0xFFu;
                    atomicAdd(&hist[bin >> 1], 1u << ((bin & 1) * 16));
                }
        }
        __syncthreads();
        unsigned cb = (hist[t >> 1] >> ((t & 1) * 16)) & 0xFFFFu;
        unsigned s = cb;
#pragma unroll
        for (int d = 1; d < 32; d <<= 1) {
            unsigned o = __shfl_down_sync(0xFFFFFFFFu, s, d);
            if (lane + d < 32) s += o;
        }
        if (lane == 0) wsum[w] = s;
        __syncthreads();
        if (t == 0) {
            unsigned tmp[8], run = 0;
            for (int i = 7; i >= 0; i--) { tmp[i] = run; run += wsum[i]; }
            for (int i = 0; i < 8; i++) wsum[i] = tmp[i];
        }
        __syncthreads();
        unsigned above = (s - cb) + wsum[w];
        if (above < need && above + cb >= need) {
            s_prefix = prefix | ((unsigned)t << shift);
            s_need   = need - above;
            s_c      = cb;
        }
        __syncthreads();
        prefix = s_prefix; need = s_need; csel = s_c;
        pmask |= 0xFFu << shift;
        __syncthreads();
    }

    // ---- collect candidates (keys matching pivot prefix) ----
    if (t == 0) s_cnt = 0;
    __syncthreads();
#pragma unroll
    for (int j = 0; j < VEC; j++) {
        uint4 k = SK4[j * NTHREADS + t];
        unsigned kk[4] = {k.x, k.y, k.z, k.w};
#pragma unroll
        for (int q = 0; q < 4; q++)
            if ((kk[q] & pmask) == prefix) {
                unsigned slot = atomicAdd(&s_cnt, 1u);
                if (slot < CAP) {
                    listKey[slot] = kk[q];
                    listIdx[slot] = (unsigned short)((j * NTHREADS + t) * 4 + q);
                }
            }
    }
    __syncthreads();
    unsigned cnt = min(s_cnt, (unsigned)CAP);

    // ---- exact rank select, (key desc, index asc) == lax.top_k tie-break.
    //      Mark results by rewriting the key in smem (no flag array). ----
    for (unsigned s0 = t; s0 < cnt; s0 += NTHREADS) {
        unsigned k0 = listKey[s0];
        unsigned i0 = listIdx[s0];
        unsigned rank = 0;
        for (unsigned j2 = 0; j2 < cnt; j2++) {
            unsigned kj = listKey[j2];
            rank += (kj > k0) || (kj == k0 && listIdx[j2] < i0);
        }
        skey[i0] = (rank < need) ? 0xFFFFFFFFu : 0u;
    }
    __syncthreads();

    // ---- output: above pivot bucket -> 1; selected candidates -> 1; else 0 ----
    float4* O = (float4*)out + (size_t)row * (N_COLS / 4);
#pragma unroll
    for (int j = 0; j < VEC; j++) {
        uint4 k = SK4[j * NTHREADS + t];
        float4 v;
        v.x = (k.x == 0xFFFFFFFFu || (k.x & pmask) > prefix) ? 1.0f : 0.0f;
        v.y = (k.y == 0xFFFFFFFFu || (k.y & pmask) > prefix) ? 1.0f : 0.0f;
        v.z = (k.z == 0xFFFFFFFFu || (k.z & pmask) > prefix) ? 1.0f : 0.0f;
        v.w = (k.w == 0xFFFFFFFFu || (k.w & pmask) > prefix) ? 1.0f : 0.0f;
        O[j * NTHREADS + t] = v;
    }
}

extern "C" void kernel_launch(void* const* d_in, const int* in_sizes, int n_in,
                              void* d_out, int out_size)
{
    const float* logits = (const float*)d_in[0];
    const float* noise  = (const float*)d_in[1];
    float* out = (float*)d_out;
    int rows = in_sizes[0] / N_COLS;   // 2048
    gumbel_topk_kernel<<<rows, NTHREADS>>>(logits, noise, out);
}

// round 17
// speedup vs baseline: 1.8977x; 1.8977x over previous
#include <cuda_runtime.h>

// GumbelTopK forward == per row: 1.0 at the positions of the top-64 values of
// (logits + gumbel_noise), ties -> lowest index; 0.0 elsewhere.
// (cumsum(softmax) <= 64 is always all-ones; straight-through makes the
// forward value exactly y_hard; softmax is monotone so top_k(y)==top_k(g).)

#define NT    256
#define NC    8192
#define TOPK  64u
#define CAP   512
#define VEC   8      // float4 chunks per thread: 8192/4/256 = 8

__device__ __forceinline__ unsigned ordkey(float f) {
    unsigned u = __float_as_uint(f);
    return (u & 0x80000000u) ? ~u : (u | 0x80000000u);
}

__global__ __launch_bounds__(NT, 4) void gumbel_topk_kernel(
    const float* __restrict__ logits,
    const float* __restrict__ noise,
    float* __restrict__ out)
{
    __shared__ unsigned hist[2048];            // 8 KB; later reused as flag[8192]
    __shared__ unsigned wsum[8];
    __shared__ unsigned s_prefix, s_need, s_c, s_cnt;
    __shared__ unsigned listKey[CAP];
    __shared__ unsigned short listIdx[CAP];
    unsigned char* flag = (unsigned char*)hist;

    const int t    = threadIdx.x;
    const int lane = t & 31;
    const int w    = t >> 5;
    const int row  = blockIdx.x;

    const float4* L = (const float4*)logits + (size_t)row * (NC / 4);
    const float4* G = (const float4*)noise  + (size_t)row * (NC / 4);

    // init 2048-bin histogram (2 x uint4 per thread)
    ((uint4*)hist)[t]       = make_uint4(0, 0, 0, 0);
    ((uint4*)hist)[t + 256] = make_uint4(0, 0, 0, 0);

    // ---- load + key transform: keys in registers, NOTHING between loads ----
    unsigned key[VEC][4];
#pragma unroll
    for (int j = 0; j < VEC; j++) {
        float4 a = L[j * NT + t];
        float4 b = G[j * NT + t];
        key[j][0] = ordkey(a.x + b.x);
        key[j][1] = ordkey(a.y + b.y);
        key[j][2] = ordkey(a.z + b.z);
        key[j][3] = ordkey(a.w + b.w);
    }
    __syncthreads();

    // ---- 11-bit histogram, plain atomics (low collision at 2048 bins) ----
#pragma unroll
    for (int j = 0; j < VEC; j++)
#pragma unroll
        for (int q = 0; q < 4; q++)
            atomicAdd(&hist[key[j][q] >> 21], 1u);
    __syncthreads();

    // ---- pass-1 selection: suffix counts over 2048 bins (8 bins/thread) ----
    unsigned need = TOPK, prefix, pmask = 0xFFE00000u, csel;
    {
        uint4 h0 = ((const uint4*)hist)[2 * t];
        uint4 h1 = ((const uint4*)hist)[2 * t + 1];
        unsigned c[8] = {h0.x, h0.y, h0.z, h0.w, h1.x, h1.y, h1.z, h1.w};
        unsigned g = c[0]+c[1]+c[2]+c[3]+c[4]+c[5]+c[6]+c[7];
        unsigned s = g;
#pragma unroll
        for (int d = 1; d < 32; d <<= 1) {
            unsigned o = __shfl_down_sync(0xFFFFFFFFu, s, d);
            if (lane + d < 32) s += o;
        }
        if (lane == 0) wsum[w] = s;
        __syncthreads();
        if (t == 0) {
            unsigned tmp[8], run = 0;
            for (int i = 7; i >= 0; i--) { tmp[i] = run; run += wsum[i]; }
            for (int i = 0; i < 8; i++) wsum[i] = tmp[i];
        }
        __syncthreads();
        unsigned run = (s - g) + wsum[w];          // elems in bins above my group
#pragma unroll
        for (int b2 = 7; b2 >= 0; b2--) {          // descend bins within group
            unsigned cb = c[b2];
            if (run < need && run + cb >= need) {  // unique crossing bin
                s_prefix = ((unsigned)(t * 8 + b2)) << 21;
                s_need   = need - run;
                s_c      = cb;
            }
            run += cb;
        }
        __syncthreads();
        prefix = s_prefix; need = s_need; csel = s_c;
    }
    __syncthreads();

    // ---- rare fallback refinements (only if pivot bucket > CAP) ----
    const int      fsh[3] = {13, 5, 0};
    const unsigned fmk[3] = {0xFFu, 0xFFu, 0x1Fu};
    for (int p = 0; p < 3 && csel > CAP; p++) {
        hist[t] = 0;
        __syncthreads();
        const int sh = fsh[p]; const unsigned mk = fmk[p];
#pragma unroll
        for (int j = 0; j < VEC; j++)
#pragma unroll
            for (int q = 0; q < 4; q++) {
                unsigned kk = key[j][q];
                if ((kk & pmask) == prefix)
                    atomicAdd(&hist[(kk >> sh) & mk], 1u);
            }
        __syncthreads();
        unsigned cb = hist[t];
        unsigned s = cb;
#pragma unroll
        for (int d = 1; d < 32; d <<= 1) {
            unsigned o = __shfl_down_sync(0xFFFFFFFFu, s, d);
            if (lane + d < 32) s += o;
        }
        if (lane == 0) wsum[w] = s;
        __syncthreads();
        if (t == 0) {
            unsigned tmp[8], run = 0;
            for (int i = 7; i >= 0; i--) { tmp[i] = run; run += wsum[i]; }
            for (int i = 0; i < 8; i++) wsum[i] = tmp[i];
        }
        __syncthreads();
        unsigned above = (s - cb) + wsum[w];
        if (above < need && above + cb >= need) {
            s_prefix = prefix | ((unsigned)t << sh);
            s_need   = need - above;
            s_c      = cb;
        }
        __syncthreads();
        prefix = s_prefix; need = s_need; csel = s_c;
        pmask |= mk << sh;
        __syncthreads();
    }

    // ---- collect candidates; zero their flags (flag aliases dead hist) ----
    if (t == 0) s_cnt = 0;
    __syncthreads();
#pragma unroll
    for (int j = 0; j < VEC; j++)
#pragma unroll
        for (int q = 0; q < 4; q++) {
            unsigned kk = key[j][q];
            if ((kk & pmask) == prefix) {
                unsigned idx = (unsigned)((j * NT + t) * 4 + q);
                flag[idx] = 0;
                unsigned slot = atomicAdd(&s_cnt, 1u);
                if (slot < CAP) {
                    listKey[slot] = kk;
                    listIdx[slot] = (unsigned short)idx;
                }
            }
        }
    __syncthreads();
    unsigned cnt = min(s_cnt, (unsigned)CAP);

    // ---- exact rank select, (key desc, index asc) == lax.top_k tie-break ----
    for (unsigned s0 = t; s0 < cnt; s0 += NT) {
        unsigned k0 = listKey[s0];
        unsigned i0 = listIdx[s0];
        unsigned r  = 0;
        for (unsigned j2 = 0; j2 < cnt; j2++) {
            unsigned kj = listKey[j2];
            r += (kj > k0) || (kj == k0 && listIdx[j2] < i0);
        }
        flag[i0] = (r < need) ? (unsigned char)1 : (unsigned char)0;
    }
    __syncthreads();

    // ---- output: above pivot bucket -> 1; flagged candidate -> 1; else 0 ----
    float4* O = (float4*)out + (size_t)row * (NC / 4);
#pragma unroll
    for (int j = 0; j < VEC; j++) {
        const int base = (j * NT + t) * 4;
        float4 v; unsigned km;
        km = key[j][0] & pmask;
        v.x = (km > prefix) ? 1.0f : ((km == prefix && flag[base + 0]) ? 1.0f : 0.0f);
        km = key[j][1] & pmask;
        v.y = (km > prefix) ? 1.0f : ((km == prefix && flag[base + 1]) ? 1.0f : 0.0f);
        km = key[j][2] & pmask;
        v.z = (km > prefix) ? 1.0f : ((km == prefix && flag[base + 2]) ? 1.0f : 0.0f);
        km = key[j][3] & pmask;
        v.w = (km > prefix) ? 1.0f : ((km == prefix && flag[base + 3]) ? 1.0f : 0.0f);
        O[j * NT + t] = v;
    }
}

extern "C" void kernel_launch(void* const* d_in, const int* in_sizes, int n_in,
                              void* d_out, int out_size)
{
    const float* logits = (const float*)d_in[0];
    const float* noise  = (const float*)d_in[1];
    float* out = (float*)d_out;
    int rows = in_sizes[0] / NC;   // 2048
    gumbel_topk_kernel<<<rows, NT>>>(logits, noise, out);
}